// round 1
// baseline (speedup 1.0000x reference)
#include <cuda_runtime.h>

// ---------------- problem constants ----------------
constexpr int BATCH  = 65536;
constexpr int DIN    = 2000;
constexpr int DH1    = 512;
constexpr int DH2    = 256;
constexpr int NP     = 30;    // parent classes
constexpr int NC     = 200;   // child classes
constexpr int NLAT   = 16;
constexpr int NUM_UM = 2;
constexpr int N_HOT  = 4;
constexpr int N_CH   = 12;
constexpr int N_FH   = 64;
constexpr int N_FEAT = DH2 + NP + N_CH;     // 298
constexpr int NHEAD  = NP + NC + NLAT + NUM_UM; // 248
constexpr int NHEAD_PAD = 256;

// ---------------- device scratch (no cudaMalloc allowed) ----------------
__device__ float g_z1[(size_t)BATCH * DH1];          // 134 MB
__device__ float g_head[(size_t)BATCH * NHEAD_PAD];  // 67 MB
__device__ float g_whead[DH2 * NHEAD_PAD];           // packed head weights [K=256][N=256]
__device__ float g_bhead[NHEAD_PAD];                 // packed head bias

// ---------------- packed f32x2 helpers (sm_100+ FFMA2) ----------------
typedef unsigned long long u64;

__device__ __forceinline__ u64 pk2(float x) {
    u64 r; asm("mov.b64 %0, {%1, %1};" : "=l"(r) : "f"(x)); return r;
}
__device__ __forceinline__ void fma2(u64 &d, u64 a, u64 b) {
    asm("fma.rn.f32x2 %0, %1, %2, %0;" : "+l"(d) : "l"(a), "l"(b));
}
__device__ __forceinline__ float2 up2(u64 v) {
    float2 r; asm("mov.b64 {%0, %1}, %2;" : "=f"(r.x), "=f"(r.y) : "l"(v)); return r;
}

// ---------------- weight packer for fused head GEMM ----------------
__global__ void pack_head_kernel(const float* __restrict__ Wp, const float* __restrict__ bp,
                                 const float* __restrict__ Wc, const float* __restrict__ bc,
                                 const float* __restrict__ Wlat, const float* __restrict__ blat,
                                 const float* __restrict__ Wum, const float* __restrict__ bum) {
    int idx = blockIdx.x * blockDim.x + threadIdx.x;
    if (idx >= DH2 * NHEAD_PAD) return;
    int k = idx >> 8;        // 0..255
    int c = idx & 255;       // 0..255
    float v = 0.f;
    if (c < NP)                 v = Wp[k * NP + c];
    else if (c < NP + NC)       v = Wc[k * NC + (c - NP)];
    else if (c < NP + NC + NLAT) v = Wlat[k * NLAT + (c - NP - NC)];
    else if (c < NHEAD)         v = Wum[k * NUM_UM + (c - NP - NC - NLAT)];
    g_whead[idx] = v;
    if (k == 0) {
        float b = 0.f;
        if (c < NP)                  b = bp[c];
        else if (c < NP + NC)        b = bc[c - NP];
        else if (c < NP + NC + NLAT) b = blat[c - NP - NC];
        else if (c < NHEAD)          b = bum[c - NP - NC - NLAT];
        g_bhead[c] = b;
    }
}

// ---------------- packed-f32x2 SGEMM: C = [relu](A[M,K] @ B[K,N] + bias) ----------------
// BM=BN=128, BK=8, 256 threads, 8x8 per-thread tile as 8 rows x 4 packed col-pairs.
// Requires: M % 128 == 0, N % 128 == 0, K % 8 == 0.
template <bool RELU>
__global__ __launch_bounds__(256)
void sgemm_kernel(const float* __restrict__ A, const float* __restrict__ Bw,
                  const float* __restrict__ bias, float* __restrict__ C,
                  int M, int N, int K) {
    __shared__ float As[8][128];   // transposed A tile: As[k][m]
    __shared__ float Bs[8][128];   // Bs[k][n]

    const int tid = threadIdx.x;
    const int bx = blockIdx.x;     // col tile
    const int by = blockIdx.y;     // row tile
    const int tx = tid & 15;
    const int ty = tid >> 4;
    const int rowb = ty * 8;
    const int colb = tx * 8;

    // global-load mapping
    const int am = tid >> 1;            // 0..127
    const int ak = (tid & 1) * 4;       // 0 or 4
    const int bk = tid >> 5;            // 0..7
    const int bn = (tid & 31) * 4;      // 0..124

    const float* Ap = A + (size_t)(by * 128 + am) * K + ak;
    const float* Bp = Bw + (size_t)bk * N + bx * 128 + bn;

    u64 acc[8][4];
#pragma unroll
    for (int i = 0; i < 8; i++)
#pragma unroll
        for (int j = 0; j < 4; j++) acc[i][j] = 0ull;

    float4 ra = *(const float4*)Ap;
    float4 rb = *(const float4*)Bp;

    const int ntiles = K >> 3;
    for (int t = 0; t < ntiles; t++) {
        // stage current tile into smem
        As[ak + 0][am] = ra.x;
        As[ak + 1][am] = ra.y;
        As[ak + 2][am] = ra.z;
        As[ak + 3][am] = ra.w;
        *(float4*)&Bs[bk][bn] = rb;
        __syncthreads();
        // prefetch next tile into registers (latency hidden by compute below)
        if (t + 1 < ntiles) {
            ra = *(const float4*)(Ap + (t + 1) * 8);
            rb = *(const float4*)(Bp + (size_t)(t + 1) * 8 * N);
        }
#pragma unroll
        for (int kk = 0; kk < 8; kk++) {
            float4 a0 = *(const float4*)&As[kk][rowb];
            float4 a1 = *(const float4*)&As[kk][rowb + 4];
            float av[8] = {a0.x, a0.y, a0.z, a0.w, a1.x, a1.y, a1.z, a1.w};
            u64 aa[8];
#pragma unroll
            for (int i = 0; i < 8; i++) aa[i] = pk2(av[i]);
            const u64* bp2 = (const u64*)&Bs[kk][colb];
            u64 bb[4] = {bp2[0], bp2[1], bp2[2], bp2[3]};
#pragma unroll
            for (int i = 0; i < 8; i++)
#pragma unroll
                for (int j = 0; j < 4; j++) fma2(acc[i][j], aa[i], bb[j]);
        }
        __syncthreads();
    }

    // epilogue
    const int cbase = bx * 128 + colb;
    float2 bb4[4];
#pragma unroll
    for (int j = 0; j < 4; j++) {
        bb4[j].x = bias[cbase + 2 * j];
        bb4[j].y = bias[cbase + 2 * j + 1];
    }
    const size_t rbase = (size_t)(by * 128 + rowb);
#pragma unroll
    for (int i = 0; i < 8; i++) {
        float* Crow = C + (rbase + i) * N + cbase;
#pragma unroll
        for (int j = 0; j < 4; j++) {
            float2 v = up2(acc[i][j]);
            v.x += bb4[j].x;
            v.y += bb4[j].y;
            if (RELU) { v.x = fmaxf(v.x, 0.f); v.y = fmaxf(v.y, 0.f); }
            *(float2*)(Crow + 2 * j) = v;
        }
    }
}

// ---------------- tail: argmax, output scatter, masked hotspot MLP ----------------
// one 64-thread block per row
__global__ void tail_kernel(const float* __restrict__ head,   // g_head [B][256]
                            const float* __restrict__ z,      // o_z    [B][256]
                            const float* __restrict__ cW1, const float* __restrict__ cb1,
                            const float* __restrict__ cW2, const float* __restrict__ cb2,
                            const int* __restrict__ hot, const int* __restrict__ cidx,
                            float* __restrict__ o_parent, float* __restrict__ o_corr,
                            float* __restrict__ o_lat, float* __restrict__ o_um,
                            float* __restrict__ o_mask) {
    const int row = blockIdx.x;
    const int t = threadIdx.x;     // 0..63
    __shared__ float sh[NHEAD];    // parent(30) | child(200) | lat(16) | um(2)
    __shared__ float sz[DH2];
    __shared__ float sub[N_CH];
    __shared__ float hbuf[N_FH];
    __shared__ int s_pidx;

    const float* hrow = head + (size_t)row * NHEAD_PAD;
    const float* zrow = z + (size_t)row * DH2;
    for (int i = t; i < NHEAD; i += 64) sh[i] = hrow[i];
    for (int i = t; i < DH2; i += 64) sz[i] = zrow[i];
    __syncthreads();

    if (t == 0) {
        int best = 0; float bv = sh[0];
#pragma unroll
        for (int i = 1; i < NP; i++) {
            float v = sh[i];
            if (v > bv) { bv = v; best = i; }   // first-max tie-break, matches jnp.argmax
        }
        s_pidx = best;
    }
    __syncthreads();
    const int pidx = s_pidx;

    if (t < NP)     o_parent[(size_t)row * NP + t]     = sh[t];
    if (t < NLAT)   o_lat[(size_t)row * NLAT + t]      = sh[NP + NC + t];
    if (t < NUM_UM) o_um[(size_t)row * NUM_UM + t]     = sh[NP + NC + NLAT + t];

    float active = 0.f;
    for (int n = 0; n < N_HOT; n++) {
        if (hot[n] == pidx) {            // block-uniform branch
            active = 1.f;
            if (t < N_CH) sub[t] = sh[NP + cidx[n * N_CH + t]];
            __syncthreads();
            // hidden layer: thread t computes h[t]
            const float* w1 = cW1 + (size_t)n * N_FEAT * N_FH + t;
            float acc = cb1[n * N_FH + t];
#pragma unroll 4
            for (int f = 0; f < DH2; f++) acc += sz[f] * w1[f * N_FH];
#pragma unroll
            for (int f = 0; f < NP; f++) acc += sh[f] * w1[(DH2 + f) * N_FH];
#pragma unroll
            for (int f = 0; f < N_CH; f++) acc += sub[f] * w1[(DH2 + NP + f) * N_FH];
            hbuf[t] = fmaxf(acc, 0.f);
            __syncthreads();
            // output layer + residual add (RESIDUAL_SCALE == 1)
            if (t < N_CH) {
                const float* w2 = cW2 + (size_t)n * N_FH * N_CH + t;
                float r = cb2[n * N_CH + t];
#pragma unroll
                for (int h = 0; h < N_FH; h++) r += hbuf[h] * w2[h * N_CH];
                sh[NP + cidx[n * N_CH + t]] += r;
            }
            __syncthreads();
        }
    }

    for (int i = t; i < NC; i += 64) o_corr[(size_t)row * NC + i] = sh[NP + i];
    if (t == 0) o_mask[row] = active;
}

// ---------------- launcher ----------------
extern "C" void kernel_launch(void* const* d_in, const int* in_sizes, int n_in,
                              void* d_out, int out_size) {
    const float* x    = (const float*)d_in[0];
    const float* W1   = (const float*)d_in[1];
    const float* b1   = (const float*)d_in[2];
    const float* W2   = (const float*)d_in[3];
    const float* b2   = (const float*)d_in[4];
    const float* Wp   = (const float*)d_in[5];
    const float* bp   = (const float*)d_in[6];
    const float* Wc   = (const float*)d_in[7];
    const float* bc   = (const float*)d_in[8];
    const float* Wlat = (const float*)d_in[9];
    const float* blat = (const float*)d_in[10];
    const float* Wum  = (const float*)d_in[11];
    const float* bum  = (const float*)d_in[12];
    const float* cW1  = (const float*)d_in[13];
    const float* cb1  = (const float*)d_in[14];
    const float* cW2  = (const float*)d_in[15];
    const float* cb2  = (const float*)d_in[16];
    const int*   hot  = (const int*)d_in[17];
    const int*   cidx = (const int*)d_in[18];

    float* out = (float*)d_out;
    float* o_parent = out;
    float* o_corr   = o_parent + (size_t)BATCH * NP;
    float* o_lat    = o_corr   + (size_t)BATCH * NC;
    float* o_um     = o_lat    + (size_t)BATCH * NLAT;
    float* o_z      = o_um     + (size_t)BATCH * NUM_UM;
    float* o_mask   = o_z      + (size_t)BATCH * DH2;

    void *pz1 = nullptr, *phead = nullptr, *pwh = nullptr, *pbh = nullptr;
    cudaGetSymbolAddress(&pz1, g_z1);
    cudaGetSymbolAddress(&phead, g_head);
    cudaGetSymbolAddress(&pwh, g_whead);
    cudaGetSymbolAddress(&pbh, g_bhead);
    float* z1    = (float*)pz1;
    float* headb = (float*)phead;
    float* whead = (float*)pwh;
    float* bhead = (float*)pbh;

    // pack fused head weights (tiny)
    pack_head_kernel<<<(DH2 * NHEAD_PAD + 255) / 256, 256>>>(Wp, bp, Wc, bc, Wlat, blat, Wum, bum);

    // GEMM1: z1 = relu(x @ W1 + b1)   [65536 x 512], K=2000
    sgemm_kernel<true><<<dim3(DH1 / 128, BATCH / 128), 256>>>(x, W1, b1, z1, BATCH, DH1, DIN);

    // GEMM2: z = relu(z1 @ W2 + b2)   [65536 x 256], K=512 -> straight into z output
    sgemm_kernel<true><<<dim3(DH2 / 128, BATCH / 128), 256>>>(z1, W2, b2, o_z, BATCH, DH2, DH1);

    // GEMM3: head = z @ Whead + bhead  [65536 x 256(padded)], K=256, no relu
    sgemm_kernel<false><<<dim3(NHEAD_PAD / 128, BATCH / 128), 256>>>(o_z, whead, bhead, headb, BATCH, NHEAD_PAD, DH2);

    // tail: argmax + scatter + masked hotspot correction
    tail_kernel<<<BATCH, 64>>>(headb, o_z, cW1, cb1, cW2, cb2, hot, cidx,
                               o_parent, o_corr, o_lat, o_um, o_mask);
}

// round 5
// speedup vs baseline: 1.8611x; 1.8611x over previous
#include <cuda_runtime.h>
#include <cuda_bf16.h>
#include <cstdint>

typedef unsigned int u32;
typedef unsigned long long u64;

// ---------------- problem constants ----------------
constexpr int BATCH  = 65536;
constexpr int DIN    = 2000;
constexpr int DH1    = 512;
constexpr int DH2    = 256;
constexpr int NP     = 30;
constexpr int NC     = 200;
constexpr int NLAT   = 16;
constexpr int NUM_UM = 2;
constexpr int N_HOT  = 4;
constexpr int N_CH   = 12;
constexpr int N_FH   = 64;
constexpr int N_FEAT = DH2 + NP + N_CH;          // 298
constexpr int NHEAD  = NP + NC + NLAT + NUM_UM;  // 248
constexpr int NHEAD_PAD = 256;
constexpr int K1P = 2048;                        // DIN padded to 64 multiple

// ---------------- device scratch (no cudaMalloc allowed) ----------------
__device__ __nv_bfloat16 g_a1h[(size_t)BATCH * K1P];
__device__ __nv_bfloat16 g_a1l[(size_t)BATCH * K1P];
__device__ __nv_bfloat16 g_a2h[(size_t)BATCH * DH1];
__device__ __nv_bfloat16 g_a2l[(size_t)BATCH * DH1];
__device__ __nv_bfloat16 g_a3h[(size_t)BATCH * DH2];
__device__ __nv_bfloat16 g_a3l[(size_t)BATCH * DH2];
__device__ __nv_bfloat16 g_b1h[DH1 * K1P], g_b1l[DH1 * K1P];         // W1^T split [512,2048]
__device__ __nv_bfloat16 g_b2h[DH2 * DH1], g_b2l[DH2 * DH1];         // W2^T split [256,512]
__device__ __nv_bfloat16 g_b3h[NHEAD_PAD * DH2], g_b3l[NHEAD_PAD * DH2]; // head^T split [256,256]
__device__ float g_head[(size_t)BATCH * NHEAD_PAD];
__device__ float g_bhead[NHEAD_PAD];

// ---------------- small helpers ----------------
__device__ __forceinline__ u32 smem_u32(const void* p) {
    u32 a;
    asm("{ .reg .u64 t; cvta.to.shared.u64 t, %1; cvt.u32.u64 %0, t; }" : "=r"(a) : "l"(p));
    return a;
}
__device__ __forceinline__ u32 sw128(u32 off) { return off ^ ((off >> 3) & 0x70); }

__device__ __forceinline__ void split2(float v, __nv_bfloat16& h, __nv_bfloat16& l) {
    h = __float2bfloat16(v);
    l = __float2bfloat16(v - __bfloat162float(h));
}
__device__ __forceinline__ u32 bf2u(__nv_bfloat16 a, __nv_bfloat16 b) {
    __nv_bfloat162 t; t.x = a; t.y = b;
    return *reinterpret_cast<u32*>(&t);
}

// cp.async
__device__ __forceinline__ void cp16(u32 dst, const void* src) {
    asm volatile("cp.async.cg.shared.global [%0], [%1], 16;" :: "r"(dst), "l"(src));
}
#define CP_COMMIT() asm volatile("cp.async.commit_group;" ::: "memory")
#define CP_WAIT1()  asm volatile("cp.async.wait_group 1;" ::: "memory")

// shared load / ldmatrix / mma
__device__ __forceinline__ u32 lds32(u32 a) {
    u32 v; asm volatile("ld.shared.b32 %0, [%1];" : "=r"(v) : "r"(a)); return v;
}
#define LDMX4(r, a) \
    asm volatile("ldmatrix.sync.aligned.m8n8.x4.shared.b16 {%0,%1,%2,%3}, [%4];" \
                 : "=r"((r)[0]), "=r"((r)[1]), "=r"((r)[2]), "=r"((r)[3]) : "r"(a))

__device__ __forceinline__ void mma16816(float* c, const u32* a, const u32* b) {
    asm volatile(
        "mma.sync.aligned.m16n8k16.row.col.f32.bf16.bf16.f32 "
        "{%0,%1,%2,%3}, {%4,%5,%6,%7}, {%8,%9}, {%0,%1,%2,%3};"
        : "+f"(c[0]), "+f"(c[1]), "+f"(c[2]), "+f"(c[3])
        : "r"(a[0]), "r"(a[1]), "r"(a[2]), "r"(a[3]), "r"(b[0]), "r"(b[1]));
}

// ---------------- split-bf16 tensor-core GEMM (mma.sync) ----------------
// D[m,n] = sum_k (Ah+Al)[m,k]*(Bh+Bl)[n,k]   (Al*Bl dropped, ~2^-16 rel)
// CTA tile 128x128, 256 threads = 8 warps in 2(M) x 4(N); warp tile 64x32.
// K staged in chunks of 64 (3-stage cp.async pipeline, 64KB/stage).
// SMEM stage layout: [Ah 16K][Al 16K][Bh 16K][Bl 16K], rows of 128B, sw128.
// MODE bits: 1 = relu, 2 = write fp32 Cf, 4 = write bf16 split Oh/Ol
template <int MODE>
__global__ __launch_bounds__(256, 1)
void tc_gemm(const __nv_bfloat16* __restrict__ Ah, const __nv_bfloat16* __restrict__ Al,
             const __nv_bfloat16* __restrict__ Bh, const __nv_bfloat16* __restrict__ Bl,
             const float* __restrict__ bias,
             float* __restrict__ Cf,
             __nv_bfloat16* __restrict__ Oh, __nv_bfloat16* __restrict__ Ol,
             int Kp, int N, int T) {
    extern __shared__ char dsm[];
    const u32 db = (smem_u32(dsm) + 1023) & ~1023u;

    const int tid  = threadIdx.x;
    const int lane = tid & 31;
    const int wid  = tid >> 5;
    const int wm   = wid & 1;      // 0..1 -> 64-row half
    const int wn   = wid >> 1;     // 0..3 -> 32-col quarter
    const int mbase = blockIdx.y * 128;
    const int nbase = blockIdx.x * 128;

    // global load mapping: thread handles row tid>>1, half-row (tid&1)*32 elems
    const int lrow = tid >> 1;
    const int lhalf = tid & 1;
    const __nv_bfloat16* pAh = Ah + (size_t)(mbase + lrow) * Kp + lhalf * 32;
    const __nv_bfloat16* pAl = Al + (size_t)(mbase + lrow) * Kp + lhalf * 32;
    const __nv_bfloat16* pBh = Bh + (size_t)(nbase + lrow) * Kp + lhalf * 32;
    const __nv_bfloat16* pBl = Bl + (size_t)(nbase + lrow) * Kp + lhalf * 32;
    const u32 rb = lrow * 128 + lhalf * 64;

    auto issue_loads = [&](int t) {
        const u32 bA = db + (t % 3) * 65536;
        const int ko = t * 64;
#pragma unroll
        for (int i = 0; i < 4; i++) {
            const u32 so = sw128(rb + i * 16);
            cp16(bA + so,         pAh + ko + i * 8);
            cp16(bA + 16384 + so, pAl + ko + i * 8);
            cp16(bA + 32768 + so, pBh + ko + i * 8);
            cp16(bA + 49152 + so, pBl + ko + i * 8);
        }
        CP_COMMIT();
    };

    float acc[4][4][4] = {};

    issue_loads(0);
    issue_loads(1);

    for (int t = 0; t < T; t++) {
        CP_WAIT1();          // stage t fully resident (this thread's groups)
        __syncthreads();     // all threads' pieces of stage t resident
        if (t + 2 < T) issue_loads(t + 2);
        else CP_COMMIT();    // keep group counting uniform

        const u32 bA   = db + (t % 3) * 65536;
        const u32 bAlo = bA + 16384;
        const u32 bB   = bA + 32768;
        const u32 bBlo = bA + 49152;

#pragma unroll
        for (int kk = 0; kk < 4; kk++) {
            // A fragments via ldmatrix.x4 (m16k16 each)
            u32 afh[4][4], afl[4][4];
#pragma unroll
            for (int mf = 0; mf < 4; mf++) {
                const u32 so = sw128((u32)(wm * 64 + mf * 16 + (lane & 15)) * 128
                                     + kk * 32 + ((lane >> 4) << 4));
                LDMX4(afh[mf], bA + so);
                LDMX4(afl[mf], bAlo + so);
            }
            // B fragments via direct LDS.32 (n8k16: b0 = k{2j,2j+1}, b1 = k{2j+8,2j+9} at n=lane/4)
            u32 bfh[4][2], bfl[4][2];
#pragma unroll
            for (int nf = 0; nf < 4; nf++) {
                const u32 base = (u32)(wn * 32 + nf * 8 + (lane >> 2)) * 128
                                 + kk * 32 + (lane & 3) * 4;
                const u32 r0 = sw128(base);
                const u32 r1 = sw128(base + 16);
                bfh[nf][0] = lds32(bB + r0);
                bfh[nf][1] = lds32(bB + r1);
                bfl[nf][0] = lds32(bBlo + r0);
                bfl[nf][1] = lds32(bBlo + r1);
            }
#pragma unroll
            for (int mf = 0; mf < 4; mf++)
#pragma unroll
                for (int nf = 0; nf < 4; nf++) {
                    mma16816(acc[mf][nf], afh[mf], bfh[nf]);
                    mma16816(acc[mf][nf], afl[mf], bfh[nf]);
                    mma16816(acc[mf][nf], afh[mf], bfl[nf]);
                }
        }
    }

    // ---------------- epilogue ----------------
#pragma unroll
    for (int nf = 0; nf < 4; nf++) {
        const int colg = nbase + wn * 32 + nf * 8 + ((lane & 3) << 1);
        const float b0 = bias[colg];
        const float b1 = bias[colg + 1];
#pragma unroll
        for (int mf = 0; mf < 4; mf++) {
            const size_t r0 = (size_t)(mbase + wm * 64 + mf * 16 + (lane >> 2));
            const size_t r1 = r0 + 8;
            float v00 = acc[mf][nf][0] + b0;
            float v01 = acc[mf][nf][1] + b1;
            float v10 = acc[mf][nf][2] + b0;
            float v11 = acc[mf][nf][3] + b1;
            if (MODE & 1) {
                v00 = fmaxf(v00, 0.f); v01 = fmaxf(v01, 0.f);
                v10 = fmaxf(v10, 0.f); v11 = fmaxf(v11, 0.f);
            }
            if (MODE & 2) {
                *(float2*)(Cf + r0 * N + colg) = make_float2(v00, v01);
                *(float2*)(Cf + r1 * N + colg) = make_float2(v10, v11);
            }
            if (MODE & 4) {
                __nv_bfloat16 h0, l0, h1, l1;
                split2(v00, h0, l0); split2(v01, h1, l1);
                *(u32*)(Oh + r0 * N + colg) = bf2u(h0, h1);
                *(u32*)(Ol + r0 * N + colg) = bf2u(l0, l1);
                split2(v10, h0, l0); split2(v11, h1, l1);
                *(u32*)(Oh + r1 * N + colg) = bf2u(h0, h1);
                *(u32*)(Ol + r1 * N + colg) = bf2u(l0, l1);
            }
        }
    }
}

// ---------------- conversion kernels ----------------
// x [B, 2000] fp32 -> g_a1h/g_a1l [B, 2048] bf16 (zero-padded)
__global__ void conv_x_kernel(const float* __restrict__ x) {
    const size_t idx = (size_t)blockIdx.x * 256 + threadIdx.x;   // B * 256 threads
    const int row = (int)(idx >> 8);
    const int k0 = (int)(idx & 255) * 8;
    float v[8];
    if (k0 < DIN) {   // DIN = 2000 divisible by 8 -> full vector
        const float* p = x + (size_t)row * DIN + k0;
        float4 a = *(const float4*)p;
        float4 b = *(const float4*)(p + 4);
        v[0]=a.x; v[1]=a.y; v[2]=a.z; v[3]=a.w; v[4]=b.x; v[5]=b.y; v[6]=b.z; v[7]=b.w;
    } else {
#pragma unroll
        for (int i = 0; i < 8; i++) v[i] = 0.f;
    }
    u32 hw[4], lw[4];
#pragma unroll
    for (int j = 0; j < 4; j++) {
        __nv_bfloat16 h0, l0, h1, l1;
        split2(v[2*j], h0, l0);
        split2(v[2*j+1], h1, l1);
        hw[j] = bf2u(h0, h1);
        lw[j] = bf2u(l0, l1);
    }
    const size_t off = (size_t)row * K1P + k0;
    *(uint4*)(g_a1h + off) = make_uint4(hw[0], hw[1], hw[2], hw[3]);
    *(uint4*)(g_a1l + off) = make_uint4(lw[0], lw[1], lw[2], lw[3]);
}

// W1 [2000, 512] -> g_b1h/l [512, 2048] transposed split
__global__ void conv_w1_kernel(const float* __restrict__ W1) {
    const int idx = blockIdx.x * 256 + threadIdx.x;
    if (idx >= DH1 * K1P) return;
    const int n = idx / K1P, k = idx % K1P;
    const float v = (k < DIN) ? W1[(size_t)k * DH1 + n] : 0.f;
    __nv_bfloat16 h, l; split2(v, h, l);
    g_b1h[idx] = h; g_b1l[idx] = l;
}

// W2 [512, 256] -> g_b2h/l [256, 512]
__global__ void conv_w2_kernel(const float* __restrict__ W2) {
    const int idx = blockIdx.x * 256 + threadIdx.x;
    if (idx >= DH2 * DH1) return;
    const int n = idx / DH1, k = idx % DH1;
    const float v = W2[(size_t)k * DH2 + n];
    __nv_bfloat16 h, l; split2(v, h, l);
    g_b2h[idx] = h; g_b2l[idx] = l;
}

// packed head weights -> g_b3h/l [256(units), 256(K)], + g_bhead
__global__ void conv_w3_kernel(const float* __restrict__ Wp, const float* __restrict__ bp,
                               const float* __restrict__ Wc, const float* __restrict__ bc,
                               const float* __restrict__ Wlat, const float* __restrict__ blat,
                               const float* __restrict__ Wum, const float* __restrict__ bum) {
    const int idx = blockIdx.x * 256 + threadIdx.x;
    if (idx >= NHEAD_PAD * DH2) return;
    const int c = idx / DH2;      // head unit (output col)
    const int k = idx % DH2;      // input feature
    float v = 0.f;
    if (c < NP)                       v = Wp[(size_t)k * NP + c];
    else if (c < NP + NC)             v = Wc[(size_t)k * NC + (c - NP)];
    else if (c < NP + NC + NLAT)      v = Wlat[(size_t)k * NLAT + (c - NP - NC)];
    else if (c < NHEAD)               v = Wum[(size_t)k * NUM_UM + (c - NP - NC - NLAT)];
    __nv_bfloat16 h, l; split2(v, h, l);
    g_b3h[idx] = h; g_b3l[idx] = l;
    if (k == 0) {
        float b = 0.f;
        if (c < NP)                   b = bp[c];
        else if (c < NP + NC)         b = bc[c - NP];
        else if (c < NP + NC + NLAT)  b = blat[c - NP - NC];
        else if (c < NHEAD)           b = bum[c - NP - NC - NLAT];
        g_bhead[c] = b;
    }
}

// ---------------- tail: argmax, scatter, masked hotspot MLP ----------------
__global__ void tail_kernel(const float* __restrict__ head,   // g_head [B][256]
                            const float* __restrict__ z,      // o_z    [B][256]
                            const float* __restrict__ cW1, const float* __restrict__ cb1,
                            const float* __restrict__ cW2, const float* __restrict__ cb2,
                            const int* __restrict__ hot, const int* __restrict__ cidx,
                            float* __restrict__ o_parent, float* __restrict__ o_corr,
                            float* __restrict__ o_lat, float* __restrict__ o_um,
                            float* __restrict__ o_mask) {
    const int row = blockIdx.x;
    const int t = threadIdx.x;     // 0..63
    __shared__ float sh[NHEAD];
    __shared__ float sz[DH2];
    __shared__ float sub[N_CH];
    __shared__ float hbuf[N_FH];
    __shared__ int s_pidx;

    const float* hrow = head + (size_t)row * NHEAD_PAD;
    const float* zrow = z + (size_t)row * DH2;
    for (int i = t; i < NHEAD; i += 64) sh[i] = hrow[i];
    for (int i = t; i < DH2; i += 64) sz[i] = zrow[i];
    __syncthreads();

    if (t == 0) {
        int best = 0; float bv = sh[0];
#pragma unroll
        for (int i = 1; i < NP; i++) {
            float v = sh[i];
            if (v > bv) { bv = v; best = i; }   // first-max tie-break, matches jnp.argmax
        }
        s_pidx = best;
    }
    __syncthreads();
    const int pidx = s_pidx;

    if (t < NP)     o_parent[(size_t)row * NP + t]   = sh[t];
    if (t < NLAT)   o_lat[(size_t)row * NLAT + t]    = sh[NP + NC + t];
    if (t < NUM_UM) o_um[(size_t)row * NUM_UM + t]   = sh[NP + NC + NLAT + t];

    float active = 0.f;
    for (int n = 0; n < N_HOT; n++) {
        if (hot[n] == pidx) {            // block-uniform branch
            active = 1.f;
            if (t < N_CH) sub[t] = sh[NP + cidx[n * N_CH + t]];
            __syncthreads();
            const float* w1 = cW1 + (size_t)n * N_FEAT * N_FH + t;
            float acc = cb1[n * N_FH + t];
#pragma unroll 4
            for (int f = 0; f < DH2; f++) acc += sz[f] * w1[f * N_FH];
#pragma unroll
            for (int f = 0; f < NP; f++) acc += sh[f] * w1[(DH2 + f) * N_FH];
#pragma unroll
            for (int f = 0; f < N_CH; f++) acc += sub[f] * w1[(DH2 + NP + f) * N_FH];
            hbuf[t] = fmaxf(acc, 0.f);
            __syncthreads();
            if (t < N_CH) {
                const float* w2 = cW2 + (size_t)n * N_FH * N_CH + t;
                float r = cb2[n * N_CH + t];
#pragma unroll
                for (int h = 0; h < N_FH; h++) r += hbuf[h] * w2[h * N_CH];
                sh[NP + cidx[n * N_CH + t]] += r;
            }
            __syncthreads();
        }
    }

    for (int i = t; i < NC; i += 64) o_corr[(size_t)row * NC + i] = sh[NP + i];
    if (t == 0) o_mask[row] = active;
}

// ---------------- launcher ----------------
extern "C" void kernel_launch(void* const* d_in, const int* in_sizes, int n_in,
                              void* d_out, int out_size) {
    const float* x    = (const float*)d_in[0];
    const float* W1   = (const float*)d_in[1];
    const float* b1   = (const float*)d_in[2];
    const float* W2   = (const float*)d_in[3];
    const float* b2   = (const float*)d_in[4];
    const float* Wp   = (const float*)d_in[5];
    const float* bp   = (const float*)d_in[6];
    const float* Wc   = (const float*)d_in[7];
    const float* bc   = (const float*)d_in[8];
    const float* Wlat = (const float*)d_in[9];
    const float* blat = (const float*)d_in[10];
    const float* Wum  = (const float*)d_in[11];
    const float* bum  = (const float*)d_in[12];
    const float* cW1  = (const float*)d_in[13];
    const float* cb1  = (const float*)d_in[14];
    const float* cW2  = (const float*)d_in[15];
    const float* cb2  = (const float*)d_in[16];
    const int*   hot  = (const int*)d_in[17];
    const int*   cidx = (const int*)d_in[18];

    float* out = (float*)d_out;
    float* o_parent = out;
    float* o_corr   = o_parent + (size_t)BATCH * NP;
    float* o_lat    = o_corr   + (size_t)BATCH * NC;
    float* o_um     = o_lat    + (size_t)BATCH * NLAT;
    float* o_z      = o_um     + (size_t)BATCH * NUM_UM;
    float* o_mask   = o_z      + (size_t)BATCH * DH2;

    // symbol addresses
    void *pa1h, *pa1l, *pa2h, *pa2l, *pa3h, *pa3l;
    void *pb1h, *pb1l, *pb2h, *pb2l, *pb3h, *pb3l, *phead, *pbh;
    cudaGetSymbolAddress(&pa1h, g_a1h); cudaGetSymbolAddress(&pa1l, g_a1l);
    cudaGetSymbolAddress(&pa2h, g_a2h); cudaGetSymbolAddress(&pa2l, g_a2l);
    cudaGetSymbolAddress(&pa3h, g_a3h); cudaGetSymbolAddress(&pa3l, g_a3l);
    cudaGetSymbolAddress(&pb1h, g_b1h); cudaGetSymbolAddress(&pb1l, g_b1l);
    cudaGetSymbolAddress(&pb2h, g_b2h); cudaGetSymbolAddress(&pb2l, g_b2l);
    cudaGetSymbolAddress(&pb3h, g_b3h); cudaGetSymbolAddress(&pb3l, g_b3l);
    cudaGetSymbolAddress(&phead, g_head); cudaGetSymbolAddress(&pbh, g_bhead);

    const int SMEMSZ = 3 * 65536 + 1024;
    cudaFuncSetAttribute(tc_gemm<5>, cudaFuncAttributeMaxDynamicSharedMemorySize, SMEMSZ);
    cudaFuncSetAttribute(tc_gemm<7>, cudaFuncAttributeMaxDynamicSharedMemorySize, SMEMSZ);
    cudaFuncSetAttribute(tc_gemm<2>, cudaFuncAttributeMaxDynamicSharedMemorySize, SMEMSZ);

    // conversions
    conv_x_kernel<<<BATCH, 256>>>(x);
    conv_w1_kernel<<<(DH1 * K1P + 255) / 256, 256>>>(W1);
    conv_w2_kernel<<<(DH2 * DH1 + 255) / 256, 256>>>(W2);
    conv_w3_kernel<<<(NHEAD_PAD * DH2 + 255) / 256, 256>>>(Wp, bp, Wc, bc, Wlat, blat, Wum, bum);

    // GEMM1: relu(x @ W1 + b1) -> split bf16 (g_a2h/l)   [65536 x 512], K=2048
    tc_gemm<5><<<dim3(DH1 / 128, BATCH / 128), 256, SMEMSZ>>>(
        (const __nv_bfloat16*)pa1h, (const __nv_bfloat16*)pa1l,
        (const __nv_bfloat16*)pb1h, (const __nv_bfloat16*)pb1l,
        b1, nullptr, (__nv_bfloat16*)pa2h, (__nv_bfloat16*)pa2l, K1P, DH1, K1P / 64);

    // GEMM2: relu(z1 @ W2 + b2) -> o_z fp32 + split bf16 (g_a3h/l)  [65536 x 256], K=512
    tc_gemm<7><<<dim3(DH2 / 128, BATCH / 128), 256, SMEMSZ>>>(
        (const __nv_bfloat16*)pa2h, (const __nv_bfloat16*)pa2l,
        (const __nv_bfloat16*)pb2h, (const __nv_bfloat16*)pb2l,
        b2, o_z, (__nv_bfloat16*)pa3h, (__nv_bfloat16*)pa3l, DH1, DH2, DH1 / 64);

    // GEMM3: z @ Whead + bhead -> g_head fp32  [65536 x 256], K=256
    tc_gemm<2><<<dim3(NHEAD_PAD / 128, BATCH / 128), 256, SMEMSZ>>>(
        (const __nv_bfloat16*)pa3h, (const __nv_bfloat16*)pa3l,
        (const __nv_bfloat16*)pb3h, (const __nv_bfloat16*)pb3l,
        (const float*)pbh, (float*)phead, nullptr, nullptr, DH2, NHEAD_PAD, DH2 / 64);

    // tail
    tail_kernel<<<BATCH, 64>>>((const float*)phead, o_z, cW1, cb1, cW2, cb2, hot, cidx,
                               o_parent, o_corr, o_lat, o_um, o_mask);
}